// round 7
// baseline (speedup 1.0000x reference)
#include <cuda_runtime.h>
#include <math.h>

#define B_  32
#define T0_ 2048
#define T1_ 2044
#define T2_ 2040
#define T3_ 2034

// ---------------- scratch (device globals; no allocations allowed) ----------
__device__ float g_xT  [20   * B_ * T0_];
__device__ float g_act1[512  * B_ * T1_];
__device__ float g_act2[512  * B_ * T2_];
__device__ float g_act3[512  * B_ * T3_];
__device__ float g_act4[512  * B_ * T3_];
__device__ float g_act5[1500 * B_ * T3_];
__device__ float g_scl [1500];
__device__ float g_shf [1500];
__device__ float g_pool[B_ * 3000];
__device__ float g_y1  [B_ * 512];
__device__ float g_y2  [B_ * 512];

// ---------------- transpose x[b][t][f] -> xT[f][b][t] -----------------------
__global__ void transpose_x(const float* __restrict__ x, float* __restrict__ xT) {
    int idx = blockIdx.x * blockDim.x + threadIdx.x;
    const int total = B_ * T0_ * 20;
    if (idx >= total) return;
    int f = idx % 20;
    int t = (idx / 20) % T0_;
    int b = idx / (20 * T0_);
    xT[((size_t)f * B_ + b) * T0_ + t] = x[idx];
}

// ---------------- TF32 helpers ----------------------------------------------
__device__ __forceinline__ unsigned f2tf32(float v) {
    unsigned r;
    asm("cvt.rna.tf32.f32 %0, %1;" : "=r"(r) : "f"(v));
    return r;
}
__device__ __forceinline__ void split_tf32(float v, unsigned &hi, unsigned &lo) {
    hi = f2tf32(v);
    lo = f2tf32(v - __uint_as_float(hi));
}

__device__ __forceinline__ void mma_tf32(float c[4],
                                         unsigned a0, unsigned a1, unsigned a2, unsigned a3,
                                         unsigned b0, unsigned b1) {
    asm("mma.sync.aligned.m16n8k8.row.col.f32.tf32.tf32.f32 "
        "{%0,%1,%2,%3}, {%4,%5,%6,%7}, {%8,%9}, {%0,%1,%2,%3};"
        : "+f"(c[0]), "+f"(c[1]), "+f"(c[2]), "+f"(c[3])
        : "r"(a0), "r"(a1), "r"(a2), "r"(a3), "r"(b0), "r"(b1));
}

// ---------------- fused (bn-affine on input) + splice + 1x1 conv GEMM --------
// 3xTF32 split-precision tensor-core GEMM.
// Block 128x128x16, 4 warps (128 thr), warp tile 64x64.
// Shared layout interleaves hi/lo: As[k][2m]=hi, As[k][2m+1]=lo -> LDS.64 frags.
// Pitch 264 words => fragment bank = (8*tg + 2*g) mod 32 : conflict-free.
#define TBM 128
#define TBN 128
#define TBK 16
#define PITCH 264   // 2*128 + 8

__global__ __launch_bounds__(128, 2)
void gemm_splice(const float* __restrict__ W, const float* __restrict__ bias,
                 const float* __restrict__ X, float* __restrict__ Y,
                 const float* __restrict__ scl, const float* __restrict__ shf,
                 int M, int K, int C, int offStride,
                 int Tin, int Tout, int actMode)
{
    __shared__ unsigned As[TBK][PITCH];
    __shared__ unsigned Bs[TBK][PITCH];

    const int b     = blockIdx.z;
    const int m0    = blockIdx.y * TBM;
    const int tbase = blockIdx.x * TBN;
    const int tid   = threadIdx.x;

    const int lane  = tid & 31;
    const int warp  = tid >> 5;          // 0..3
    const int g     = lane >> 2;         // 0..7
    const int tg    = lane & 3;          // 0..3
    const int wm    = (warp & 1) * 64;
    const int wn    = (warp >> 1) * 64;

    const float* Xb = X + (size_t)b * Tin;

    float acc[4][8][4];
#pragma unroll
    for (int mi = 0; mi < 4; mi++)
#pragma unroll
        for (int ni = 0; ni < 8; ni++)
#pragma unroll
            for (int r = 0; r < 4; r++) acc[mi][ni][r] = 0.f;

    // producer indexing
    const int aM    = m0 + tid;            // A: one M-row per thread, 16 k's
    const int bKrow = tid >> 3;            // B: k-row 0..15
    const int bC0   = (tid & 7) * 16;      // B: 16 t's per thread

    for (int k0 = 0; k0 < K; k0 += TBK) {
        // ---- A tile: W[aM][k0..k0+15], split, interleaved store ----
        {
            float v[16];
#pragma unroll
            for (int jj = 0; jj < 4; jj++) {
                float4 t4 = make_float4(0.f, 0.f, 0.f, 0.f);
                if (aM < M && k0 + jj * 4 + 4 <= K)   // K % 4 == 0 for all layers
                    t4 = *(const float4*)(W + (size_t)aM * K + k0 + jj * 4);
                v[jj*4+0] = t4.x; v[jj*4+1] = t4.y; v[jj*4+2] = t4.z; v[jj*4+3] = t4.w;
            }
#pragma unroll
            for (int k = 0; k < 16; k++) {
                unsigned h, l; split_tf32(v[k], h, l);
                *(uint2*)&As[k][2 * tid] = make_uint2(h, l);
            }
        }
        // ---- B tile: splice gather + folded bn affine, split, interleaved ----
        {
            int k = k0 + bKrow;
            bool kv = (k < K);
            int f = 0, off = 0;
            if (kv) { f = k / C; off = (k - f * C) * offStride; }
            float sA = 1.f, sB = 0.f;
            if (kv && scl) { sA = scl[f]; sB = shf[f]; }
            const float* src = Xb + (size_t)f * (B_ * (size_t)Tin) + off + tbase + bC0;
#pragma unroll
            for (int j = 0; j < 16; j += 2) {
                int t0 = tbase + bC0 + j;
                float v0 = (kv && t0     < Tout) ? fmaf(src[j],     sA, sB) : 0.f;
                float v1 = (kv && t0 + 1 < Tout) ? fmaf(src[j + 1], sA, sB) : 0.f;
                unsigned h0, l0, h1, l1;
                split_tf32(v0, h0, l0);
                split_tf32(v1, h1, l1);
                *(uint4*)&Bs[bKrow][2 * (bC0 + j)] = make_uint4(h0, l0, h1, l1);
            }
        }
        __syncthreads();

#pragma unroll
        for (int kk = 0; kk < TBK; kk += 8) {
            unsigned afh[4][4], afl[4][4], bfh[8][2], bfl[8][2];
#pragma unroll
            for (int mi = 0; mi < 4; mi++) {
                int m2 = 2 * (wm + mi * 16 + g);
                uint2 a00 = *(const uint2*)&As[kk + tg    ][m2];
                uint2 a10 = *(const uint2*)&As[kk + tg    ][m2 + 16];
                uint2 a01 = *(const uint2*)&As[kk + tg + 4][m2];
                uint2 a11 = *(const uint2*)&As[kk + tg + 4][m2 + 16];
                afh[mi][0] = a00.x; afh[mi][1] = a10.x; afh[mi][2] = a01.x; afh[mi][3] = a11.x;
                afl[mi][0] = a00.y; afl[mi][1] = a10.y; afl[mi][2] = a01.y; afl[mi][3] = a11.y;
            }
#pragma unroll
            for (int ni = 0; ni < 8; ni++) {
                int n2 = 2 * (wn + ni * 8 + g);
                uint2 b0 = *(const uint2*)&Bs[kk + tg    ][n2];
                uint2 b1 = *(const uint2*)&Bs[kk + tg + 4][n2];
                bfh[ni][0] = b0.x; bfh[ni][1] = b1.x;
                bfl[ni][0] = b0.y; bfl[ni][1] = b1.y;
            }
#pragma unroll
            for (int mi = 0; mi < 4; mi++)
#pragma unroll
                for (int ni = 0; ni < 8; ni++) {
                    mma_tf32(acc[mi][ni], afh[mi][0], afh[mi][1], afh[mi][2], afh[mi][3],
                             bfh[ni][0], bfh[ni][1]);
                    mma_tf32(acc[mi][ni], afh[mi][0], afh[mi][1], afh[mi][2], afh[mi][3],
                             bfl[ni][0], bfl[ni][1]);
                    mma_tf32(acc[mi][ni], afl[mi][0], afl[mi][1], afl[mi][2], afl[mi][3],
                             bfh[ni][0], bfh[ni][1]);
                }
        }
        __syncthreads();
    }

    // ---- epilogue: bias + activation, write [M][B][Tout] ----
    const size_t strideY = (size_t)B_ * Tout;
#pragma unroll
    for (int mi = 0; mi < 4; mi++) {
        int mA = m0 + wm + mi * 16 + g;
        int mB = mA + 8;
        float biA = (mA < M) ? bias[mA] : 0.f;
        float biB = (mB < M) ? bias[mB] : 0.f;
#pragma unroll
        for (int ni = 0; ni < 8; ni++) {
            int t = tbase + wn + ni * 8 + tg * 2;
            if (t >= Tout) continue;
            if (mA < M) {
                float2 v;
                v.x = fmaxf(acc[mi][ni][0] + biA, 0.f);
                v.y = fmaxf(acc[mi][ni][1] + biA, 0.f);
                if (actMode) { v.x = fminf(v.x, 6.f); v.y = fminf(v.y, 6.f); }
                *(float2*)&Y[(size_t)mA * strideY + (size_t)b * Tout + t] = v;
            }
            if (mB < M) {
                float2 v;
                v.x = fmaxf(acc[mi][ni][2] + biB, 0.f);
                v.y = fmaxf(acc[mi][ni][3] + biB, 0.f);
                if (actMode) { v.x = fminf(v.x, 6.f); v.y = fminf(v.y, 6.f); }
                *(float2*)&Y[(size_t)mB * strideY + (size_t)b * Tout + t] = v;
            }
        }
    }
}

// ---------------- per-channel batch-norm stats (over B*T) -------------------
__global__ void channel_stats(const float* __restrict__ Y, int N,
                              const float* __restrict__ gam, const float* __restrict__ bet,
                              float* __restrict__ scl, float* __restrict__ shf)
{
    int c = blockIdx.x;
    const float4* p = (const float4*)(Y + (size_t)c * N);
    int n4 = N >> 2;
    float s1 = 0.f, s2 = 0.f;
    for (int i = threadIdx.x; i < n4; i += blockDim.x) {
        float4 v = p[i];
        s1 += v.x + v.y + v.z + v.w;
        s2 += v.x*v.x + v.y*v.y + v.z*v.z + v.w*v.w;
    }
    __shared__ float r1[256], r2[256];
    r1[threadIdx.x] = s1; r2[threadIdx.x] = s2;
    __syncthreads();
    for (int s = 128; s > 0; s >>= 1) {
        if (threadIdx.x < s) {
            r1[threadIdx.x] += r1[threadIdx.x + s];
            r2[threadIdx.x] += r2[threadIdx.x + s];
        }
        __syncthreads();
    }
    if (threadIdx.x == 0) {
        float m   = r1[0] / (float)N;
        float var = r2[0] / (float)N - m * m;
        float inv = rsqrtf(var + 1e-5f);
        float g   = gam ? gam[c] : 1.f;
        float be  = bet ? bet[c] : 0.f;
        float A   = g * inv;
        scl[c] = A;
        shf[c] = be - m * A;
    }
}

// ---------------- stats pooling over time, with folded bn affine ------------
__global__ void pool_stats(const float* __restrict__ A,
                           const float* __restrict__ scl, const float* __restrict__ shf,
                           float* __restrict__ P)
{
    int c = blockIdx.x;
    int b = blockIdx.y;
    const float* p = A + ((size_t)c * B_ + b) * T3_;
    float s1 = 0.f, s2 = 0.f;
    for (int i = threadIdx.x; i < T3_; i += blockDim.x) {
        float v = p[i]; s1 += v; s2 += v * v;
    }
    __shared__ float r1[128], r2[128];
    r1[threadIdx.x] = s1; r2[threadIdx.x] = s2;
    __syncthreads();
    for (int s = 64; s > 0; s >>= 1) {
        if (threadIdx.x < s) {
            r1[threadIdx.x] += r1[threadIdx.x + s];
            r2[threadIdx.x] += r2[threadIdx.x + s];
        }
        __syncthreads();
    }
    if (threadIdx.x == 0) {
        float m   = r1[0] / (float)T3_;
        float var = (r2[0] - (float)T3_ * m * m) / (float)(T3_ - 1);
        float a = scl[c], d = shf[c];
        P[b * 3000 + c]        = a * m + d;
        P[b * 3000 + 1500 + c] = fabsf(a) * sqrtf(fmaxf(var, 0.f));
    }
}

// ---------------- dense + relu6 (one warp per output) -----------------------
__global__ void dense_relu6(const float* __restrict__ W, const float* __restrict__ bias,
                            const float* __restrict__ X, float* __restrict__ Y,
                            int M, int K)
{
    int gw   = (blockIdx.x * blockDim.x + threadIdx.x) >> 5;
    int lane = threadIdx.x & 31;
    if (gw >= B_ * M) return;
    int b = gw / M, o = gw - b * M;
    const float* w = W + (size_t)o * K;
    const float* x = X + (size_t)b * K;
    float s = 0.f;
    for (int k = lane; k < K; k += 32) s += w[k] * x[k];
#pragma unroll
    for (int off = 16; off; off >>= 1) s += __shfl_xor_sync(0xffffffffu, s, off);
    if (lane == 0) {
        float v = s + bias[o];
        Y[(size_t)b * M + o] = fminf(fmaxf(v, 0.f), 6.f);
    }
}

// ---------------- batch-norm over batch dim (B=32 == warp) ------------------
__global__ void bn_batch(const float* __restrict__ Y, const float* __restrict__ gam,
                         const float* __restrict__ bet, float* __restrict__ Out, int M)
{
    int o    = (blockIdx.x * blockDim.x + threadIdx.x) >> 5;
    int lane = threadIdx.x & 31;
    if (o >= M) return;
    float v  = Y[(size_t)lane * M + o];
    float s1 = v, s2 = v * v;
#pragma unroll
    for (int off = 16; off; off >>= 1) {
        s1 += __shfl_xor_sync(0xffffffffu, s1, off);
        s2 += __shfl_xor_sync(0xffffffffu, s2, off);
    }
    float m   = s1 * (1.f / 32.f);
    float var = s2 * (1.f / 32.f) - m * m;
    float r   = rsqrtf(var + 1e-5f);
    Out[(size_t)lane * M + o] = (v - m) * r * gam[o] + bet[o];
}

// ---------------- launch ----------------------------------------------------
extern "C" void kernel_launch(void* const* d_in, const int* in_sizes, int n_in,
                              void* d_out, int out_size)
{
    const float* x     = (const float*)d_in[0];
    const float* h1_w  = (const float*)d_in[1];
    const float* h1_b  = (const float*)d_in[2];
    const float* h2_w  = (const float*)d_in[3];
    const float* h2_b  = (const float*)d_in[4];
    const float* bn2_g = (const float*)d_in[5];
    const float* bn2_b = (const float*)d_in[6];
    const float* h3_w  = (const float*)d_in[7];
    const float* h3_b  = (const float*)d_in[8];
    const float* bn3_g = (const float*)d_in[9];
    const float* bn3_b = (const float*)d_in[10];
    const float* h4_w  = (const float*)d_in[11];
    const float* h4_b  = (const float*)d_in[12];
    const float* bn4_g = (const float*)d_in[13];
    const float* bn4_b = (const float*)d_in[14];
    const float* h5_w  = (const float*)d_in[15];
    const float* h5_b  = (const float*)d_in[16];
    const float* bn5_g = (const float*)d_in[17];
    const float* bn5_b = (const float*)d_in[18];
    const float* l1_w  = (const float*)d_in[19];
    const float* l1_b  = (const float*)d_in[20];
    const float* bn6_g = (const float*)d_in[21];
    const float* bn6_b = (const float*)d_in[22];
    const float* l2_w  = (const float*)d_in[23];
    const float* l2_b  = (const float*)d_in[24];
    const float* bn7_g = (const float*)d_in[25];
    const float* bn7_b = (const float*)d_in[26];

    float *xT, *a1, *a2, *a3, *a4, *a5, *scl, *shf, *pool, *y1, *y2;
    cudaGetSymbolAddress((void**)&xT,   g_xT);
    cudaGetSymbolAddress((void**)&a1,   g_act1);
    cudaGetSymbolAddress((void**)&a2,   g_act2);
    cudaGetSymbolAddress((void**)&a3,   g_act3);
    cudaGetSymbolAddress((void**)&a4,   g_act4);
    cudaGetSymbolAddress((void**)&a5,   g_act5);
    cudaGetSymbolAddress((void**)&scl,  g_scl);
    cudaGetSymbolAddress((void**)&shf,  g_shf);
    cudaGetSymbolAddress((void**)&pool, g_pool);
    cudaGetSymbolAddress((void**)&y1,   g_y1);
    cudaGetSymbolAddress((void**)&y2,   g_y2);

    const int N1 = B_ * T1_;
    const int N2 = B_ * T2_;
    const int N3 = B_ * T3_;

    transpose_x<<<(B_ * T0_ * 20 + 255) / 256, 256>>>(x, xT);

    gemm_splice<<<dim3((T1_ + 127) / 128, 4, B_), 128>>>(
        h1_w, h1_b, xT, a1, nullptr, nullptr, 512, 100, 5, 1, T0_, T1_, 0);
    channel_stats<<<512, 256>>>(a1, N1, nullptr, nullptr, scl, shf);

    gemm_splice<<<dim3((T2_ + 127) / 128, 4, B_), 128>>>(
        h2_w, h2_b, a1, a2, scl, shf, 512, 1536, 3, 2, T1_, T2_, 0);
    channel_stats<<<512, 256>>>(a2, N2, bn2_g, bn2_b, scl, shf);

    gemm_splice<<<dim3((T3_ + 127) / 128, 4, B_), 128>>>(
        h3_w, h3_b, a2, a3, scl, shf, 512, 1536, 3, 3, T2_, T3_, 0);
    channel_stats<<<512, 256>>>(a3, N3, bn3_g, bn3_b, scl, shf);

    gemm_splice<<<dim3((T3_ + 127) / 128, 4, B_), 128>>>(
        h4_w, h4_b, a3, a4, scl, shf, 512, 512, 1, 0, T3_, T3_, 1);
    channel_stats<<<512, 256>>>(a4, N3, bn4_g, bn4_b, scl, shf);

    gemm_splice<<<dim3((T3_ + 127) / 128, 12, B_), 128>>>(
        h5_w, h5_b, a4, a5, scl, shf, 1500, 512, 1, 0, T3_, T3_, 1);
    channel_stats<<<1500, 256>>>(a5, N3, bn5_g, bn5_b, scl, shf);

    pool_stats<<<dim3(1500, B_), 128>>>(a5, scl, shf, pool);

    dense_relu6<<<(B_ * 512 * 32 + 255) / 256, 256>>>(l1_w, l1_b, pool, y1, 512, 3000);
    bn_batch<<<(512 * 32 + 255) / 256, 256>>>(y1, bn6_g, bn6_b, y1, 512);

    dense_relu6<<<(B_ * 512 * 32 + 255) / 256, 256>>>(l2_w, l2_b, y1, y2, 512, 512);
    bn_batch<<<(512 * 32 + 255) / 256, 256>>>(y2, bn7_g, bn7_b, (float*)d_out, 512);
}

// round 8
// speedup vs baseline: 1.7974x; 1.7974x over previous
#include <cuda_runtime.h>
#include <math.h>

#define B_  32
#define T0_ 2048
#define T1_ 2044
#define T2_ 2040
#define T3_ 2034

// ---------------- scratch (device globals; no allocations allowed) ----------
__device__ float g_xT  [20   * B_ * T0_];
__device__ float g_act1[512  * B_ * T1_];
__device__ float g_act2[512  * B_ * T2_];
__device__ float g_act3[512  * B_ * T3_];
__device__ float g_act4[512  * B_ * T3_];
__device__ float g_act5[1500 * B_ * T3_];
__device__ float g_scl [1500];
__device__ float g_shf [1500];
__device__ float g_pool[B_ * 3000];
__device__ float g_y1  [B_ * 512];
__device__ float g_y2  [B_ * 512];

// ---------------- transpose x[b][t][f] -> xT[f][b][t] -----------------------
__global__ void transpose_x(const float* __restrict__ x, float* __restrict__ xT) {
    int idx = blockIdx.x * blockDim.x + threadIdx.x;
    const int total = B_ * T0_ * 20;
    if (idx >= total) return;
    int f = idx % 20;
    int t = (idx / 20) % T0_;
    int b = idx / (20 * T0_);
    xT[((size_t)f * B_ + b) * T0_ + t] = x[idx];
}

// ---------------- TF32 helpers ----------------------------------------------
__device__ __forceinline__ unsigned f2tf32(float v) {
    unsigned r;
    asm("cvt.rna.tf32.f32 %0, %1;" : "=r"(r) : "f"(v));
    return r;
}
__device__ __forceinline__ void split_tf32(float v, unsigned &hi, unsigned &lo) {
    hi = f2tf32(v);
    lo = f2tf32(v - __uint_as_float(hi));
}

__device__ __forceinline__ void mma_tf32(float c[4],
                                         unsigned a0, unsigned a1, unsigned a2, unsigned a3,
                                         unsigned b0, unsigned b1) {
    asm("mma.sync.aligned.m16n8k8.row.col.f32.tf32.tf32.f32 "
        "{%0,%1,%2,%3}, {%4,%5,%6,%7}, {%8,%9}, {%0,%1,%2,%3};"
        : "+f"(c[0]), "+f"(c[1]), "+f"(c[2]), "+f"(c[3])
        : "r"(a0), "r"(a1), "r"(a2), "r"(a3), "r"(b0), "r"(b1));
}

// ---------------- fused (bn-affine on input) + splice + 1x1 conv GEMM --------
// 3xTF32 split-precision tensor-core GEMM.
// Block 128x128x16, 8 warps (256 thr), warp tile 64x32  (the R6 shape).
// Shared holds RAW fp32 (half the bytes of hi/lo); hi/lo split happens at
// fragment-load time in registers. Pad 8 -> frag bank = 8*tg+g : conflict-free.
#define TBM 128
#define TBN 128
#define TBK 16
#define PAD 8

__global__ __launch_bounds__(256, 2)
void gemm_splice(const float* __restrict__ W, const float* __restrict__ bias,
                 const float* __restrict__ X, float* __restrict__ Y,
                 const float* __restrict__ scl, const float* __restrict__ shf,
                 int M, int K, int C, int offStride,
                 int Tin, int Tout, int actMode)
{
    __shared__ float As[TBK][TBM + PAD];
    __shared__ float Bs[TBK][TBN + PAD];

    const int b     = blockIdx.z;
    const int m0    = blockIdx.y * TBM;
    const int tbase = blockIdx.x * TBN;
    const int tid   = threadIdx.x;

    const int lane  = tid & 31;
    const int warp  = tid >> 5;
    const int g     = lane >> 2;        // 0..7
    const int tg    = lane & 3;         // 0..3
    const int wm    = (warp & 1) * 64;
    const int wn    = (warp >> 1) * 32;

    const float* Xb = X + (size_t)b * Tin;

    float acc[4][4][4];
#pragma unroll
    for (int mi = 0; mi < 4; mi++)
#pragma unroll
        for (int ni = 0; ni < 4; ni++)
#pragma unroll
            for (int r = 0; r < 4; r++) acc[mi][ni][r] = 0.f;

    const int aRow  = tid >> 1;
    const int aCol0 = (tid & 1) * 8;
    const int bRow  = tid >> 4;
    const int bCol0 = (tid & 15) * 8;

    for (int k0 = 0; k0 < K; k0 += TBK) {
        // ---- load W tile (zero-padded), raw fp32 ----
        {
            int m = m0 + aRow;
#pragma unroll
            for (int j = 0; j < 8; j++) {
                int k = k0 + aCol0 + j;
                As[aCol0 + j][aRow] = (k < K && m < M) ? W[(size_t)m * K + k] : 0.f;
            }
        }
        // ---- load X tile with splice gather + folded bn affine, raw fp32 ----
        {
            int k = k0 + bRow;
            bool kv = (k < K);
            int f = 0, off = 0;
            if (kv) { f = k / C; off = (k - f * C) * offStride; }
            float sA = 1.f, sB = 0.f;
            if (kv && scl) { sA = scl[f]; sB = shf[f]; }
            const float* src = Xb + (size_t)f * (B_ * (size_t)Tin) + off + tbase + bCol0;
            float v[8];
#pragma unroll
            for (int j = 0; j < 8; j++) {
                int t = tbase + bCol0 + j;
                v[j] = (kv && t < Tout) ? fmaf(src[j], sA, sB) : 0.f;
            }
            *(float4*)&Bs[bRow][bCol0]     = make_float4(v[0], v[1], v[2], v[3]);
            *(float4*)&Bs[bRow][bCol0 + 4] = make_float4(v[4], v[5], v[6], v[7]);
        }
        __syncthreads();

#pragma unroll
        for (int kk = 0; kk < TBK; kk += 8) {
            unsigned afh[4][4], afl[4][4], bfh[4][2], bfl[4][2];
#pragma unroll
            for (int mi = 0; mi < 4; mi++) {
                int m = wm + mi * 16 + g;
                float r0 = As[kk + tg    ][m];
                float r1 = As[kk + tg    ][m + 8];
                float r2 = As[kk + tg + 4][m];
                float r3 = As[kk + tg + 4][m + 8];
                split_tf32(r0, afh[mi][0], afl[mi][0]);
                split_tf32(r1, afh[mi][1], afl[mi][1]);
                split_tf32(r2, afh[mi][2], afl[mi][2]);
                split_tf32(r3, afh[mi][3], afl[mi][3]);
            }
#pragma unroll
            for (int ni = 0; ni < 4; ni++) {
                int n = wn + ni * 8 + g;
                float r0 = Bs[kk + tg    ][n];
                float r1 = Bs[kk + tg + 4][n];
                split_tf32(r0, bfh[ni][0], bfl[ni][0]);
                split_tf32(r1, bfh[ni][1], bfl[ni][1]);
            }
#pragma unroll
            for (int mi = 0; mi < 4; mi++)
#pragma unroll
                for (int ni = 0; ni < 4; ni++) {
                    mma_tf32(acc[mi][ni], afh[mi][0], afh[mi][1], afh[mi][2], afh[mi][3],
                             bfh[ni][0], bfh[ni][1]);
                    mma_tf32(acc[mi][ni], afh[mi][0], afh[mi][1], afh[mi][2], afh[mi][3],
                             bfl[ni][0], bfl[ni][1]);
                    mma_tf32(acc[mi][ni], afl[mi][0], afl[mi][1], afl[mi][2], afl[mi][3],
                             bfh[ni][0], bfh[ni][1]);
                }
        }
        __syncthreads();
    }

    // ---- epilogue: bias + activation, write [M][B][Tout] ----
    const size_t strideY = (size_t)B_ * Tout;
#pragma unroll
    for (int mi = 0; mi < 4; mi++) {
        int mA = m0 + wm + mi * 16 + g;
        int mB = mA + 8;
        float biA = (mA < M) ? bias[mA] : 0.f;
        float biB = (mB < M) ? bias[mB] : 0.f;
#pragma unroll
        for (int ni = 0; ni < 4; ni++) {
            int t = tbase + wn + ni * 8 + tg * 2;
            if (t >= Tout) continue;
            if (mA < M) {
                float2 v;
                v.x = fmaxf(acc[mi][ni][0] + biA, 0.f);
                v.y = fmaxf(acc[mi][ni][1] + biA, 0.f);
                if (actMode) { v.x = fminf(v.x, 6.f); v.y = fminf(v.y, 6.f); }
                *(float2*)&Y[(size_t)mA * strideY + (size_t)b * Tout + t] = v;
            }
            if (mB < M) {
                float2 v;
                v.x = fmaxf(acc[mi][ni][2] + biB, 0.f);
                v.y = fmaxf(acc[mi][ni][3] + biB, 0.f);
                if (actMode) { v.x = fminf(v.x, 6.f); v.y = fminf(v.y, 6.f); }
                *(float2*)&Y[(size_t)mB * strideY + (size_t)b * Tout + t] = v;
            }
        }
    }
}

// ---------------- per-channel batch-norm stats (over B*T) -------------------
__global__ void channel_stats(const float* __restrict__ Y, int N,
                              const float* __restrict__ gam, const float* __restrict__ bet,
                              float* __restrict__ scl, float* __restrict__ shf)
{
    int c = blockIdx.x;
    const float4* p = (const float4*)(Y + (size_t)c * N);
    int n4 = N >> 2;
    float s1 = 0.f, s2 = 0.f;
    for (int i = threadIdx.x; i < n4; i += blockDim.x) {
        float4 v = p[i];
        s1 += v.x + v.y + v.z + v.w;
        s2 += v.x*v.x + v.y*v.y + v.z*v.z + v.w*v.w;
    }
    __shared__ float r1[256], r2[256];
    r1[threadIdx.x] = s1; r2[threadIdx.x] = s2;
    __syncthreads();
    for (int s = 128; s > 0; s >>= 1) {
        if (threadIdx.x < s) {
            r1[threadIdx.x] += r1[threadIdx.x + s];
            r2[threadIdx.x] += r2[threadIdx.x + s];
        }
        __syncthreads();
    }
    if (threadIdx.x == 0) {
        float m   = r1[0] / (float)N;
        float var = r2[0] / (float)N - m * m;
        float inv = rsqrtf(var + 1e-5f);
        float g   = gam ? gam[c] : 1.f;
        float be  = bet ? bet[c] : 0.f;
        float A   = g * inv;
        scl[c] = A;
        shf[c] = be - m * A;
    }
}

// ---------------- stats pooling over time, with folded bn affine ------------
__global__ void pool_stats(const float* __restrict__ A,
                           const float* __restrict__ scl, const float* __restrict__ shf,
                           float* __restrict__ P)
{
    int c = blockIdx.x;
    int b = blockIdx.y;
    const float* p = A + ((size_t)c * B_ + b) * T3_;
    float s1 = 0.f, s2 = 0.f;
    for (int i = threadIdx.x; i < T3_; i += blockDim.x) {
        float v = p[i]; s1 += v; s2 += v * v;
    }
    __shared__ float r1[128], r2[128];
    r1[threadIdx.x] = s1; r2[threadIdx.x] = s2;
    __syncthreads();
    for (int s = 64; s > 0; s >>= 1) {
        if (threadIdx.x < s) {
            r1[threadIdx.x] += r1[threadIdx.x + s];
            r2[threadIdx.x] += r2[threadIdx.x + s];
        }
        __syncthreads();
    }
    if (threadIdx.x == 0) {
        float m   = r1[0] / (float)T3_;
        float var = (r2[0] - (float)T3_ * m * m) / (float)(T3_ - 1);
        float a = scl[c], d = shf[c];
        P[b * 3000 + c]        = a * m + d;
        P[b * 3000 + 1500 + c] = fabsf(a) * sqrtf(fmaxf(var, 0.f));
    }
}

// ---------------- dense + relu6 (one warp per output) -----------------------
__global__ void dense_relu6(const float* __restrict__ W, const float* __restrict__ bias,
                            const float* __restrict__ X, float* __restrict__ Y,
                            int M, int K)
{
    int gw   = (blockIdx.x * blockDim.x + threadIdx.x) >> 5;
    int lane = threadIdx.x & 31;
    if (gw >= B_ * M) return;
    int b = gw / M, o = gw - b * M;
    const float* w = W + (size_t)o * K;
    const float* x = X + (size_t)b * K;
    float s = 0.f;
    for (int k = lane; k < K; k += 32) s += w[k] * x[k];
#pragma unroll
    for (int off = 16; off; off >>= 1) s += __shfl_xor_sync(0xffffffffu, s, off);
    if (lane == 0) {
        float v = s + bias[o];
        Y[(size_t)b * M + o] = fminf(fmaxf(v, 0.f), 6.f);
    }
}

// ---------------- batch-norm over batch dim (B=32 == warp) ------------------
__global__ void bn_batch(const float* __restrict__ Y, const float* __restrict__ gam,
                         const float* __restrict__ bet, float* __restrict__ Out, int M)
{
    int o    = (blockIdx.x * blockDim.x + threadIdx.x) >> 5;
    int lane = threadIdx.x & 31;
    if (o >= M) return;
    float v  = Y[(size_t)lane * M + o];
    float s1 = v, s2 = v * v;
#pragma unroll
    for (int off = 16; off; off >>= 1) {
        s1 += __shfl_xor_sync(0xffffffffu, s1, off);
        s2 += __shfl_xor_sync(0xffffffffu, s2, off);
    }
    float m   = s1 * (1.f / 32.f);
    float var = s2 * (1.f / 32.f) - m * m;
    float r   = rsqrtf(var + 1e-5f);
    Out[(size_t)lane * M + o] = (v - m) * r * gam[o] + bet[o];
}

// ---------------- launch ----------------------------------------------------
extern "C" void kernel_launch(void* const* d_in, const int* in_sizes, int n_in,
                              void* d_out, int out_size)
{
    const float* x     = (const float*)d_in[0];
    const float* h1_w  = (const float*)d_in[1];
    const float* h1_b  = (const float*)d_in[2];
    const float* h2_w  = (const float*)d_in[3];
    const float* h2_b  = (const float*)d_in[4];
    const float* bn2_g = (const float*)d_in[5];
    const float* bn2_b = (const float*)d_in[6];
    const float* h3_w  = (const float*)d_in[7];
    const float* h3_b  = (const float*)d_in[8];
    const float* bn3_g = (const float*)d_in[9];
    const float* bn3_b = (const float*)d_in[10];
    const float* h4_w  = (const float*)d_in[11];
    const float* h4_b  = (const float*)d_in[12];
    const float* bn4_g = (const float*)d_in[13];
    const float* bn4_b = (const float*)d_in[14];
    const float* h5_w  = (const float*)d_in[15];
    const float* h5_b  = (const float*)d_in[16];
    const float* bn5_g = (const float*)d_in[17];
    const float* bn5_b = (const float*)d_in[18];
    const float* l1_w  = (const float*)d_in[19];
    const float* l1_b  = (const float*)d_in[20];
    const float* bn6_g = (const float*)d_in[21];
    const float* bn6_b = (const float*)d_in[22];
    const float* l2_w  = (const float*)d_in[23];
    const float* l2_b  = (const float*)d_in[24];
    const float* bn7_g = (const float*)d_in[25];
    const float* bn7_b = (const float*)d_in[26];

    float *xT, *a1, *a2, *a3, *a4, *a5, *scl, *shf, *pool, *y1, *y2;
    cudaGetSymbolAddress((void**)&xT,   g_xT);
    cudaGetSymbolAddress((void**)&a1,   g_act1);
    cudaGetSymbolAddress((void**)&a2,   g_act2);
    cudaGetSymbolAddress((void**)&a3,   g_act3);
    cudaGetSymbolAddress((void**)&a4,   g_act4);
    cudaGetSymbolAddress((void**)&a5,   g_act5);
    cudaGetSymbolAddress((void**)&scl,  g_scl);
    cudaGetSymbolAddress((void**)&shf,  g_shf);
    cudaGetSymbolAddress((void**)&pool, g_pool);
    cudaGetSymbolAddress((void**)&y1,   g_y1);
    cudaGetSymbolAddress((void**)&y2,   g_y2);

    const int N1 = B_ * T1_;
    const int N2 = B_ * T2_;
    const int N3 = B_ * T3_;

    transpose_x<<<(B_ * T0_ * 20 + 255) / 256, 256>>>(x, xT);

    gemm_splice<<<dim3((T1_ + 127) / 128, 4, B_), 256>>>(
        h1_w, h1_b, xT, a1, nullptr, nullptr, 512, 100, 5, 1, T0_, T1_, 0);
    channel_stats<<<512, 256>>>(a1, N1, nullptr, nullptr, scl, shf);

    gemm_splice<<<dim3((T2_ + 127) / 128, 4, B_), 256>>>(
        h2_w, h2_b, a1, a2, scl, shf, 512, 1536, 3, 2, T1_, T2_, 0);
    channel_stats<<<512, 256>>>(a2, N2, bn2_g, bn2_b, scl, shf);

    gemm_splice<<<dim3((T3_ + 127) / 128, 4, B_), 256>>>(
        h3_w, h3_b, a2, a3, scl, shf, 512, 1536, 3, 3, T2_, T3_, 0);
    channel_stats<<<512, 256>>>(a3, N3, bn3_g, bn3_b, scl, shf);

    gemm_splice<<<dim3((T3_ + 127) / 128, 4, B_), 256>>>(
        h4_w, h4_b, a3, a4, scl, shf, 512, 512, 1, 0, T3_, T3_, 1);
    channel_stats<<<512, 256>>>(a4, N3, bn4_g, bn4_b, scl, shf);

    gemm_splice<<<dim3((T3_ + 127) / 128, 12, B_), 256>>>(
        h5_w, h5_b, a4, a5, scl, shf, 1500, 512, 1, 0, T3_, T3_, 1);
    channel_stats<<<1500, 256>>>(a5, N3, bn5_g, bn5_b, scl, shf);

    pool_stats<<<dim3(1500, B_), 128>>>(a5, scl, shf, pool);

    dense_relu6<<<(B_ * 512 * 32 + 255) / 256, 256>>>(l1_w, l1_b, pool, y1, 512, 3000);
    bn_batch<<<(512 * 32 + 255) / 256, 256>>>(y1, bn6_g, bn6_b, y1, 512);

    dense_relu6<<<(B_ * 512 * 32 + 255) / 256, 256>>>(l2_w, l2_b, y1, y2, 512, 512);
    bn_batch<<<(512 * 32 + 255) / 256, 256>>>(y2, bn7_g, bn7_b, (float*)d_out, 512);
}